// round 4
// baseline (speedup 1.0000x reference)
#include <cuda_runtime.h>
#include <cstdint>

// Problem dims
#define MDIM 8192
#define NDIM 8192
#define DDIM 256
#define KSEL 256

// ---------------- static device scratch (no allocations allowed) ----------------
__device__ float g_S[(size_t)MDIM * NDIM];      // 256 MB: exp scores
__device__ float g_Rpart[MDIM * 64];            // per (row, tileCol) partial row sums
__device__ float g_Cpart[64 * NDIM];            // per (tileRow, col) partial col sums
__device__ float g_invR[MDIM];
__device__ float g_invC[NDIM];
__device__ unsigned int g_hist[8192];
__device__ unsigned int g_thresh;
__device__ int g_candCount;
#define CAND_CAP (1 << 20)
__device__ float g_candVal[CAND_CAP];
__device__ int   g_candIdx[CAND_CAP];

// ---------------- init: zero histogram + candidate counter ----------------
__global__ void spm_init_kernel() {
    int t = blockIdx.x * blockDim.x + threadIdx.x;
    if (t < 8192) g_hist[t] = 0u;
    if (t == 8192) g_candCount = 0;
}

// ---------------- GEMM + exp + deterministic row/col partial sums ----------------
// 128x128 tile per block, 256 threads, 8x8 per thread (split 4+4 layout), BK=8.
__global__ __launch_bounds__(256, 2)
void spm_gemm_exp_kernel(const float* __restrict__ A,   // ref [M, D]
                         const float* __restrict__ B) { // src [N, D]
    const int bx = blockIdx.x;        // n tile
    const int by = blockIdx.y;        // m tile
    const int tid = threadIdx.x;
    const int ti = tid >> 4;          // 0..15
    const int tj = tid & 15;          // 0..15
    const int m0 = by * 128;
    const int n0 = bx * 128;

    __shared__ float As[2][8][132];
    __shared__ float Bs[2][8][132];
    __shared__ float redR[128 * 17];
    __shared__ float redC[128 * 17];

    const int lrow = tid >> 1;        // 0..127
    const int lk = (tid & 1) * 4;     // 0 or 4
    const float* Aptr = A + (size_t)(m0 + lrow) * DDIM + lk;
    const float* Bptr = B + (size_t)(n0 + lrow) * DDIM + lk;

    float acc[8][8];
#pragma unroll
    for (int r = 0; r < 8; r++)
#pragma unroll
        for (int c = 0; c < 8; c++) acc[r][c] = 0.0f;

    // prologue: chunk 0
    {
        float4 a4 = *(const float4*)(Aptr);
        float4 b4 = *(const float4*)(Bptr);
        As[0][lk + 0][lrow] = a4.x; As[0][lk + 1][lrow] = a4.y;
        As[0][lk + 2][lrow] = a4.z; As[0][lk + 3][lrow] = a4.w;
        Bs[0][lk + 0][lrow] = b4.x; Bs[0][lk + 1][lrow] = b4.y;
        Bs[0][lk + 2][lrow] = b4.z; Bs[0][lk + 3][lrow] = b4.w;
    }
    __syncthreads();

    for (int kt = 0; kt < 32; ++kt) {
        const int cur = kt & 1;
        float4 an, bn;
        if (kt < 31) {
            an = *(const float4*)(Aptr + (kt + 1) * 8);
            bn = *(const float4*)(Bptr + (kt + 1) * 8);
        }
#pragma unroll
        for (int kk = 0; kk < 8; ++kk) {
            float4 a0 = *(const float4*)&As[cur][kk][ti * 4];
            float4 a1 = *(const float4*)&As[cur][kk][64 + ti * 4];
            float4 b0 = *(const float4*)&Bs[cur][kk][tj * 4];
            float4 b1 = *(const float4*)&Bs[cur][kk][64 + tj * 4];
            float a[8] = {a0.x, a0.y, a0.z, a0.w, a1.x, a1.y, a1.z, a1.w};
            float b[8] = {b0.x, b0.y, b0.z, b0.w, b1.x, b1.y, b1.z, b1.w};
#pragma unroll
            for (int r = 0; r < 8; r++)
#pragma unroll
                for (int c = 0; c < 8; c++) acc[r][c] = fmaf(a[r], b[c], acc[r][c]);
        }
        if (kt < 31) {
            __syncthreads();
            const int nxt = cur ^ 1;
            As[nxt][lk + 0][lrow] = an.x; As[nxt][lk + 1][lrow] = an.y;
            As[nxt][lk + 2][lrow] = an.z; As[nxt][lk + 3][lrow] = an.w;
            Bs[nxt][lk + 0][lrow] = bn.x; Bs[nxt][lk + 1][lrow] = bn.y;
            Bs[nxt][lk + 2][lrow] = bn.z; Bs[nxt][lk + 3][lrow] = bn.w;
            __syncthreads();
        }
    }

    // epilogue: exp, store S, and deterministic row/col partials
    float ex[8][8];
    float rps[8], cps[8];
#pragma unroll
    for (int r = 0; r < 8; r++) rps[r] = 0.0f;
#pragma unroll
    for (int c = 0; c < 8; c++) cps[c] = 0.0f;

#pragma unroll
    for (int r = 0; r < 8; r++) {
#pragma unroll
        for (int c = 0; c < 8; c++) {
            float e = expf(2.0f * acc[r][c] - 2.0f);
            ex[r][c] = e;
            rps[r] += e;
            cps[c] += e;
        }
    }

#pragma unroll
    for (int r = 0; r < 8; r++) {
        const int lr = (r < 4) ? (ti * 4 + r) : (64 + ti * 4 + (r - 4));
        const int gr = m0 + lr;
        float* Srow = g_S + (size_t)gr * NDIM + n0;
        float4 s0 = make_float4(ex[r][0], ex[r][1], ex[r][2], ex[r][3]);
        float4 s1 = make_float4(ex[r][4], ex[r][5], ex[r][6], ex[r][7]);
        *(float4*)(Srow + tj * 4) = s0;
        *(float4*)(Srow + 64 + tj * 4) = s1;
        redR[lr * 17 + tj] = rps[r];
    }
#pragma unroll
    for (int c = 0; c < 8; c++) {
        const int lc = (c < 4) ? (tj * 4 + c) : (64 + tj * 4 + (c - 4));
        redC[lc * 17 + ti] = cps[c];
    }
    __syncthreads();

    if (tid < 128) {
        const int lr = tid;
        float s = 0.0f;
#pragma unroll
        for (int j = 0; j < 16; j++) s += redR[lr * 17 + j];
        g_Rpart[(size_t)(m0 + lr) * 64 + bx] = s;
    } else {
        const int lc = tid - 128;
        float s = 0.0f;
#pragma unroll
        for (int j = 0; j < 16; j++) s += redC[lc * 17 + j];
        g_Cpart[(size_t)by * NDIM + (n0 + lc)] = s;
    }
}

// ---------------- deterministic reduction of row/col sums -> reciprocals ----------------
__global__ void spm_reduce_rc_kernel() {
    int t = blockIdx.x * blockDim.x + threadIdx.x;
    if (t < MDIM) {
        float s = 0.0f;
        const float* p = g_Rpart + (size_t)t * 64;
#pragma unroll 8
        for (int i = 0; i < 64; i++) s += p[i];
        g_invR[t] = 1.0f / s;
    } else if (t < MDIM + NDIM) {
        int n = t - MDIM;
        float s = 0.0f;
        for (int i = 0; i < 64; i++) s += g_Cpart[(size_t)i * NDIM + n];
        g_invC[n] = 1.0f / s;
    }
}

// ---------------- histogram of v = S^2 * invR * invC over float-bit buckets ----------------
__global__ void spm_hist_kernel() {
    __shared__ unsigned int h[8192];
    for (int i = threadIdx.x; i < 8192; i += 256) h[i] = 0u;
    __syncthreads();

    const float4* S4 = (const float4*)g_S;
    const size_t base4 = (size_t)blockIdx.x * 4096;
#pragma unroll 4
    for (int j = 0; j < 16; j++) {
        size_t idx4 = base4 + (size_t)j * 256 + threadIdx.x;
        float4 s = S4[idx4];
        size_t i0 = idx4 * 4;
        int m = (int)(i0 >> 13);
        int n = (int)(i0 & 8191);
        float fr = g_invR[m];
        float v0 = s.x * s.x * fr * g_invC[n + 0];
        float v1 = s.y * s.y * fr * g_invC[n + 1];
        float v2 = s.z * s.z * fr * g_invC[n + 2];
        float v3 = s.w * s.w * fr * g_invC[n + 3];
        atomicAdd(&h[min(__float_as_uint(v0) >> 18, 8191u)], 1u);
        atomicAdd(&h[min(__float_as_uint(v1) >> 18, 8191u)], 1u);
        atomicAdd(&h[min(__float_as_uint(v2) >> 18, 8191u)], 1u);
        atomicAdd(&h[min(__float_as_uint(v3) >> 18, 8191u)], 1u);
    }
    __syncthreads();
    for (int i = threadIdx.x; i < 8192; i += 256) {
        unsigned int c = h[i];
        if (c) atomicAdd(&g_hist[i], c);
    }
}

// ---------------- find threshold bucket such that cum count >= 256 ----------------
__global__ void spm_thresh_kernel() {
    if (threadIdx.x == 0) {
        unsigned int cum = 0;
        int b = 8191;
        for (; b >= 0; b--) {
            cum += g_hist[b];
            if (cum >= KSEL) break;
        }
        if (b < 0) b = 0;
        g_thresh = ((unsigned int)b) << 18;
    }
}

// ---------------- gather candidates >= threshold ----------------
__global__ void spm_select_kernel() {
    const unsigned int thr = g_thresh;
    const float4* S4 = (const float4*)g_S;
    const size_t base4 = (size_t)blockIdx.x * 4096;
#pragma unroll 4
    for (int j = 0; j < 16; j++) {
        size_t idx4 = base4 + (size_t)j * 256 + threadIdx.x;
        float4 s = S4[idx4];
        size_t i0 = idx4 * 4;
        int m = (int)(i0 >> 13);
        int n = (int)(i0 & 8191);
        float fr = g_invR[m];
        float v[4];
        v[0] = s.x * s.x * fr * g_invC[n + 0];
        v[1] = s.y * s.y * fr * g_invC[n + 1];
        v[2] = s.z * s.z * fr * g_invC[n + 2];
        v[3] = s.w * s.w * fr * g_invC[n + 3];
#pragma unroll
        for (int u = 0; u < 4; u++) {
            if (__float_as_uint(v[u]) >= thr) {
                int p = atomicAdd(&g_candCount, 1);
                if (p < CAND_CAP) {
                    g_candVal[p] = v[u];
                    g_candIdx[p] = (int)(i0 + u);
                }
            }
        }
    }
}

// ---------------- exact rank-based top-256 (matches lax.top_k tie-break) ----------------
__global__ void spm_topk_kernel(float* __restrict__ out) {
    int K = g_candCount;
    if (K > CAND_CAP) K = CAND_CAP;
    for (int c = threadIdx.x; c < K; c += blockDim.x) {
        const float vc = g_candVal[c];
        const int ic = g_candIdx[c];
        int rank = 0;
        for (int j = 0; j < K; j++) {
            const float vj = g_candVal[j];
            const int ij = g_candIdx[j];
            rank += (vj > vc) || (vj == vc && ij < ic);
        }
        if (rank < KSEL) {
            out[rank]            = (float)(ic >> 13);   // ref index = i // 8192
            out[KSEL + rank]     = (float)(ic & 8191);  // src index = i % 8192
            out[2 * KSEL + rank] = vc;                  // score
        }
    }
}

// ---------------- launch ----------------
extern "C" void kernel_launch(void* const* d_in, const int* in_sizes, int n_in,
                              void* d_out, int out_size) {
    const float* ref = (const float*)d_in[0];  // [8192, 256]
    const float* src = (const float*)d_in[1];  // [8192, 256]
    float* out = (float*)d_out;                // [768]: ref_idx | src_idx | scores

    spm_init_kernel<<<33, 256>>>();
    spm_gemm_exp_kernel<<<dim3(64, 64), 256>>>(ref, src);
    spm_reduce_rc_kernel<<<64, 256>>>();
    spm_hist_kernel<<<4096, 256>>>();
    spm_thresh_kernel<<<1, 32>>>();
    spm_select_kernel<<<4096, 256>>>();
    spm_topk_kernel<<<1, 256>>>(out);
}